// round 1
// baseline (speedup 1.0000x reference)
#include <cuda_runtime.h>
#include <cuda_bf16.h>
#include <cstdint>
#include <math.h>

// ---------------- problem constants ----------------
#define BS 8192
#define LH 20
#define NF 172
#define TF 172
#define DD 860            // D = NF*3 + NF + TF
#define DH 430            // D / H
#define NROWS (BS*LH)     // 163840
#define QKVN 2580         // 3*D
#define LEF 688           // D - TF

// ---------------- scratch (__device__ globals, no cudaMalloc allowed) ----------------
__device__ float g_F[(size_t)NROWS * DD];        // 563 MB  full features
__device__ float g_QKV[(size_t)NROWS * QKVN];    // 1.69 GB qkv
__device__ float g_CTXM[(size_t)BS * DD];        // mean-over-l context
__device__ float g_OM[(size_t)BS * DD];          // out_proj(mean ctx)
__device__ float g_X[(size_t)BS * DD];           // [h_prev_left(172) | last_event_feat(688)]
__device__ float g_H1[(size_t)BS * NF];          // fc1 pre-relu

// ---------------- build kernel: gather + time encoding ----------------
__global__ void build_kernel(const int* __restrict__ nids,
                             const int* __restrict__ hist_nids,
                             const int* __restrict__ aids,
                             const int* __restrict__ eids,
                             const float* __restrict__ ts,
                             const int* __restrict__ dirs,
                             const float* __restrict__ node_emb,
                             const float* __restrict__ edge_emb,
                             const float* __restrict__ anony_emb,
                             const float* __restrict__ time_w,
                             const float* __restrict__ time_b,
                             float* __restrict__ out_pts)
{
    int row = blockIdx.x;                   // 0..NROWS-1
    int b = row / LH, l = row % LH;
    int hn  = hist_nids[row];
    int d   = dirs[row];
    int rn  = nids[b];
    int src = d ? rn : hn;
    int dst = d ? hn : rn;
    int aid = aids[row];
    int eid = eids[row];
    float tlast = ts[b*LH + (LH-1)];
    float dt = tlast - ts[row];
    bool last = (l == LH-1);
    float* Frow = g_F + (size_t)row * DD;

    for (int c = threadIdx.x; c < DD; c += blockDim.x) {
        float v;
        if      (c < 172) v = node_emb[(size_t)src*NF + c];
        else if (c < 344) v = node_emb[(size_t)dst*NF + (c-172)];
        else if (c < 516) v = anony_emb[(size_t)aid*NF + (c-344)];
        else if (c < 688) v = edge_emb[(size_t)eid*NF + (c-516)];
        else {
            int f = c - 688;
            v = cosf(dt * time_w[f] + time_b[f]);
        }
        if (last && c < LEF) {
            g_X[(size_t)b*DD + NF + c] = v;   // last_event_feat (pre-zero)
            v = 0.0f;                          // full[:, -1, :D-TF] = 0
        }
        Frow[c] = v;
    }
    if (last && threadIdx.x == 0) out_pts[b] = tlast;
}

// ---------------- tf32 tensor-core GEMM:  C[M,N] = A[M,K] @ B[N,K]^T + bias ----------------
#define BM 128
#define BN 64
#define BK 32
#define BKP 36            // padded smem stride -> conflict-free fragment loads

__device__ __forceinline__ uint32_t f2tf32(float x) {
    uint32_t u;
    asm("cvt.rna.tf32.f32 %0, %1;" : "=r"(u) : "f"(x));
    return u;
}

__device__ __forceinline__ void mma_tf32(float* c, const uint32_t* a, uint32_t b0, uint32_t b1) {
    asm volatile(
        "mma.sync.aligned.m16n8k8.row.col.f32.tf32.tf32.f32 "
        "{%0,%1,%2,%3}, {%4,%5,%6,%7}, {%8,%9}, {%0,%1,%2,%3};\n"
        : "+f"(c[0]), "+f"(c[1]), "+f"(c[2]), "+f"(c[3])
        : "r"(a[0]), "r"(a[1]), "r"(a[2]), "r"(a[3]), "r"(b0), "r"(b1));
}

// M must be a multiple of BM (true for 163840 and 8192); K multiple of 4.
__global__ void __launch_bounds__(256)
gemm_tf32(const float* __restrict__ A, const float* __restrict__ B,
          const float* __restrict__ bias, float* __restrict__ C,
          int M, int N, int K, int ldc, int relu_a)
{
    __shared__ uint32_t As[BM * BKP];
    __shared__ uint32_t Bs[BN * BKP];

    int t = threadIdx.x;
    int m0 = blockIdx.y * BM;
    int n0 = blockIdx.x * BN;

    int warp = t >> 5, lane = t & 31;
    int wm = warp & 3, wn = warp >> 2;      // 4 x 2 warp grid
    int mbase = wm * 32, nbase = wn * 32;

    float acc[2][4][4];
    #pragma unroll
    for (int mi = 0; mi < 2; mi++)
        #pragma unroll
        for (int ni = 0; ni < 4; ni++)
            #pragma unroll
            for (int r = 0; r < 4; r++) acc[mi][ni][r] = 0.0f;

    int KT = (K + BK - 1) / BK;
    for (int kt = 0; kt < KT; kt++) {
        int k0 = kt * BK;
        // stage A: 128x32 floats = 1024 float4, 4 per thread
        #pragma unroll
        for (int i = 0; i < 4; i++) {
            int id = t + i*256;
            int row = id >> 3;
            int c4 = (id & 7) * 4;
            float4 v = make_float4(0.f,0.f,0.f,0.f);
            if (k0 + c4 < K)
                v = *(const float4*)(A + (size_t)(m0+row)*K + k0 + c4);
            if (relu_a) {
                v.x = fmaxf(v.x, 0.f); v.y = fmaxf(v.y, 0.f);
                v.z = fmaxf(v.z, 0.f); v.w = fmaxf(v.w, 0.f);
            }
            uint32_t* p = &As[row*BKP + c4];
            p[0]=f2tf32(v.x); p[1]=f2tf32(v.y); p[2]=f2tf32(v.z); p[3]=f2tf32(v.w);
        }
        // stage B: 64x32 floats = 512 float4, 2 per thread
        #pragma unroll
        for (int i = 0; i < 2; i++) {
            int id = t + i*256;
            int row = id >> 3;
            int c4 = (id & 7) * 4;
            float4 v = make_float4(0.f,0.f,0.f,0.f);
            if ((n0 + row) < N && (k0 + c4) < K)
                v = *(const float4*)(B + (size_t)(n0+row)*K + k0 + c4);
            uint32_t* p = &Bs[row*BKP + c4];
            p[0]=f2tf32(v.x); p[1]=f2tf32(v.y); p[2]=f2tf32(v.z); p[3]=f2tf32(v.w);
        }
        __syncthreads();

        #pragma unroll
        for (int kk = 0; kk < 4; kk++) {
            int k8 = kk * 8;
            uint32_t a[2][4];
            #pragma unroll
            for (int mi = 0; mi < 2; mi++) {
                int r = mbase + mi*16 + (lane >> 2);
                int c = k8 + (lane & 3);
                a[mi][0] = As[r*BKP + c];
                a[mi][1] = As[(r+8)*BKP + c];
                a[mi][2] = As[r*BKP + c + 4];
                a[mi][3] = As[(r+8)*BKP + c + 4];
            }
            #pragma unroll
            for (int ni = 0; ni < 4; ni++) {
                int nb = nbase + ni*8 + (lane >> 2);
                uint32_t b0 = Bs[nb*BKP + k8 + (lane & 3)];
                uint32_t b1 = Bs[nb*BKP + k8 + (lane & 3) + 4];
                #pragma unroll
                for (int mi = 0; mi < 2; mi++)
                    mma_tf32(acc[mi][ni], a[mi], b0, b1);
            }
        }
        __syncthreads();
    }

    // epilogue: c0:(g,2t) c1:(g,2t+1) c2:(g+8,2t) c3:(g+8,2t+1)
    #pragma unroll
    for (int mi = 0; mi < 2; mi++) {
        #pragma unroll
        for (int ni = 0; ni < 4; ni++) {
            #pragma unroll
            for (int r = 0; r < 4; r++) {
                int row = m0 + mbase + mi*16 + (lane >> 2) + ((r >= 2) ? 8 : 0);
                int col = n0 + nbase + ni*8 + (lane & 3)*2 + (r & 1);
                if (col < N)
                    C[(size_t)row*ldc + col] = acc[mi][ni][r] + (bias ? bias[col] : 0.0f);
            }
        }
    }
}

// ---------------- attention + q-mean fused kernel -> ctx_mean[BS, D] ----------------
__global__ void __launch_bounds__(256)
attn_kernel(const int* __restrict__ hist_nids)
{
    __shared__ float Ks[LH * 432];
    __shared__ float sc[LH][LH];
    __shared__ float abar[LH];
    __shared__ int   msk[LH];

    int b = blockIdx.x;
    int t = threadIdx.x;
    int warp = t >> 5, lane = t & 31;
    const float* qkvb = g_QKV + (size_t)b * LH * QKVN;
    const float scale = 0.048224282f;   // 1/sqrt(430)

    if (t < LH) msk[t] = (hist_nids[b*LH + t] == 0 && t != LH-1) ? 1 : 0;

    for (int h = 0; h < 2; h++) {
        int off = h * DH;
        // load K tile into smem
        for (int i = t; i < LH*DH; i += 256) {
            int j = i / DH, dd = i % DH;
            Ks[j*432 + dd] = qkvb[(size_t)j*QKVN + DD + off + dd];
        }
        __syncthreads();

        // scores: each warp owns rows i = warp, warp+8, warp+16
        for (int i = warp; i < LH; i += 8) {
            float accj[LH];
            #pragma unroll
            for (int j = 0; j < LH; j++) accj[j] = 0.f;
            const float* qrow = qkvb + (size_t)i*QKVN + off;
            for (int dd = lane; dd < DH; dd += 32) {
                float qv = qrow[dd];
                #pragma unroll
                for (int j = 0; j < LH; j++)
                    accj[j] += qv * Ks[j*432 + dd];
            }
            #pragma unroll
            for (int j = 0; j < LH; j++) {
                float s = accj[j];
                #pragma unroll
                for (int o = 16; o > 0; o >>= 1)
                    s += __shfl_xor_sync(0xffffffffu, s, o);
                if (lane == 0) sc[i][j] = s * scale;
            }
        }
        __syncthreads();

        // masked softmax per row (warp 0, lane = row)
        if (warp == 0 && lane < LH) {
            int i = lane;
            float mx = -1e30f;
            #pragma unroll
            for (int j = 0; j < LH; j++)
                if (!msk[j]) mx = fmaxf(mx, sc[i][j]);
            float e[LH]; float s = 0.f;
            #pragma unroll
            for (int j = 0; j < LH; j++) {
                float ev = msk[j] ? 0.f : __expf(sc[i][j] - mx);
                e[j] = ev; s += ev;
            }
            float inv = 1.f / s;
            #pragma unroll
            for (int j = 0; j < LH; j++) sc[i][j] = e[j] * inv;
        }
        __syncthreads();

        // abar[j] = mean over i of attn[i][j]
        if (warp == 0 && lane < LH) {
            int j = lane; float s = 0.f;
            #pragma unroll
            for (int i = 0; i < LH; i++) s += sc[i][j];
            abar[j] = s * (1.0f / LH);
        }
        __syncthreads();

        // ctx_mean = sum_j abar[j] * v[j, :]
        for (int dd = t; dd < DH; dd += 256) {
            float s = 0.f;
            #pragma unroll
            for (int j = 0; j < LH; j++)
                s += abar[j] * qkvb[(size_t)j*QKVN + 2*DD + off + dd];
            g_CTXM[(size_t)b*DD + off + dd] = s;
        }
        __syncthreads();
    }
}

// ---------------- copy h_prev_left (g_X cols 0..171) into d_out ----------------
__global__ void copy_hl(float* __restrict__ out)
{
    int i = blockIdx.x * 256 + threadIdx.x;
    if (i < BS * NF) {
        int b = i / NF, c = i % NF;
        out[i] = g_X[(size_t)b*DD + c];
    }
}

// ---------------- launch ----------------
extern "C" void kernel_launch(void* const* d_in, const int* in_sizes, int n_in,
                              void* d_out, int out_size)
{
    const int*   nids       = (const int*)  d_in[0];
    const int*   hist_nids  = (const int*)  d_in[1];
    const int*   aids       = (const int*)  d_in[2];
    const int*   eids       = (const int*)  d_in[3];
    const float* hist_ts    = (const float*)d_in[4];
    const int*   dirs       = (const int*)  d_in[5];
    const float* node_emb   = (const float*)d_in[6];
    const float* edge_emb   = (const float*)d_in[7];
    const float* anony_emb  = (const float*)d_in[8];
    const float* time_w     = (const float*)d_in[9];
    const float* time_b     = (const float*)d_in[10];
    const float* in_proj_w  = (const float*)d_in[11];
    const float* in_proj_b  = (const float*)d_in[12];
    const float* out_proj_w = (const float*)d_in[13];
    const float* out_proj_b = (const float*)d_in[14];
    const float* outfn_w    = (const float*)d_in[15];
    const float* outfn_b    = (const float*)d_in[16];
    const float* fc1_w      = (const float*)d_in[17];
    const float* fc1_b      = (const float*)d_in[18];
    const float* fc2_w      = (const float*)d_in[19];
    const float* fc2_b      = (const float*)d_in[20];

    float* out = (float*)d_out;
    float* out_hr  = out + (size_t)BS * NF;       // h_prev_right
    float* out_pts = out + (size_t)2 * BS * NF;   // prev_ts

    float* F    = nullptr; cudaGetSymbolAddress((void**)&F,    g_F);
    float* QKV  = nullptr; cudaGetSymbolAddress((void**)&QKV,  g_QKV);
    float* CTXM = nullptr; cudaGetSymbolAddress((void**)&CTXM, g_CTXM);
    float* OM   = nullptr; cudaGetSymbolAddress((void**)&OM,   g_OM);
    float* X    = nullptr; cudaGetSymbolAddress((void**)&X,    g_X);
    float* H1   = nullptr; cudaGetSymbolAddress((void**)&H1,   g_H1);

    // 1) build full features + last_event_feat + prev_ts
    build_kernel<<<NROWS, 256>>>(nids, hist_nids, aids, eids, hist_ts, dirs,
                                 node_emb, edge_emb, anony_emb, time_w, time_b,
                                 out_pts);

    // 2) qkv = F @ in_proj_w^T + b   [163840 x 2580]
    gemm_tf32<<<dim3((QKVN+BN-1)/BN, NROWS/BM), 256>>>(
        F, in_proj_w, in_proj_b, QKV, NROWS, QKVN, DD, QKVN, 0);

    // 3) attention (+ mean over queries) -> ctx_mean [8192 x 860]
    attn_kernel<<<BS, 256>>>(hist_nids);

    // 4) om = ctx_mean @ out_proj_w^T + b   (mean commutes with linear)
    gemm_tf32<<<dim3((DD+BN-1)/BN, BS/BM), 256>>>(
        CTXM, out_proj_w, out_proj_b, OM, BS, DD, DD, DD, 0);

    // 5) h_prev_left = relu(om) @ outfn_w^T + b  -> g_X cols [0,172)
    gemm_tf32<<<dim3((NF+BN-1)/BN, BS/BM), 256>>>(
        OM, outfn_w, outfn_b, X, BS, NF, DD, DD, 1);

    // 6) copy h_prev_left to output
    copy_hl<<<(BS*NF + 255)/256, 256>>>(out);

    // 7) H1 = X @ fc1_w^T + b
    gemm_tf32<<<dim3((NF+BN-1)/BN, BS/BM), 256>>>(
        X, fc1_w, fc1_b, H1, BS, NF, DD, NF, 0);

    // 8) h_prev_right = relu(H1) @ fc2_w^T + b
    gemm_tf32<<<dim3((NF+BN-1)/BN, BS/BM), 256>>>(
        H1, fc2_w, fc2_b, out_hr, BS, NF, NF, NF, 1);
}

// round 3
// speedup vs baseline: 1.1525x; 1.1525x over previous
#include <cuda_runtime.h>
#include <cuda_bf16.h>
#include <cstdint>
#include <math.h>

// ---------------- problem constants ----------------
#define BS 8192
#define LH 20
#define NF 172
#define TF 172
#define DD 860            // D = NF*3 + NF + TF
#define DH 430            // D / H
#define NROWS (BS*LH)     // 163840
#define QKVN 2580         // 3*D
#define LEF 688           // D - TF

// weight scratch offsets (floats)
#define W_INPROJ 0
#define W_OUTPROJ (W_INPROJ + QKVN*DD)            // 2218800
#define W_OUTFN   (W_OUTPROJ + DD*DD)             // +739600
#define W_FC1     (W_OUTFN + NF*DD)               // +147920
#define W_FC2     (W_FC1 + NF*DD)                 // +147920
#define W_TOTAL   (W_FC2 + NF*NF)                 // +29584

// ---------------- scratch (__device__ globals) ----------------
__device__ float g_F[(size_t)NROWS * DD];
__device__ float g_QKV[(size_t)NROWS * QKVN];
__device__ float g_CTXM[(size_t)BS * DD];
__device__ float g_OM[(size_t)BS * DD];
__device__ float g_X[(size_t)BS * DD];
__device__ float g_H1[(size_t)BS * NF];
__device__ float g_WR[(size_t)W_TOTAL];

// ---------------- helpers ----------------
__device__ __forceinline__ uint32_t f2tf32(float x) {
    uint32_t u;
    asm("cvt.rna.tf32.f32 %0, %1;" : "=r"(u) : "f"(x));
    return u;
}
__device__ __forceinline__ float rnd_tf32(float x) {
    return __uint_as_float(f2tf32(x));
}
__device__ __forceinline__ uint32_t smem_u32(const void* p) {
    uint32_t a;
    asm("{ .reg .u64 t; cvta.to.shared.u64 t, %1; cvt.u32.u64 %0, t; }" : "=r"(a) : "l"(p));
    return a;
}
__device__ __forceinline__ void cp16(uint32_t dst, const void* src, int bytes) {
    asm volatile("cp.async.cg.shared.global [%0], [%1], 16, %2;"
                 :: "r"(dst), "l"(src), "r"(bytes));
}
__device__ __forceinline__ void cp_commit() {
    asm volatile("cp.async.commit_group;" ::: "memory");
}
template <int N>
__device__ __forceinline__ void cp_wait() {
    asm volatile("cp.async.wait_group %0;" :: "n"(N) : "memory");
}
__device__ __forceinline__ void mma_tf32(float* c, const uint32_t* a, uint32_t b0, uint32_t b1) {
    asm volatile(
        "mma.sync.aligned.m16n8k8.row.col.f32.tf32.tf32.f32 "
        "{%0,%1,%2,%3}, {%4,%5,%6,%7}, {%8,%9}, {%0,%1,%2,%3};\n"
        : "+f"(c[0]), "+f"(c[1]), "+f"(c[2]), "+f"(c[3])
        : "r"(a[0]), "r"(a[1]), "r"(a[2]), "r"(a[3]), "r"(b0), "r"(b1));
}

// ---------------- weight pre-round kernel ----------------
__global__ void round_w(const float* __restrict__ src, float* __restrict__ dst, int n)
{
    int i = blockIdx.x * 256 + threadIdx.x;
    if (i < n) dst[i] = rnd_tf32(src[i]);
}

// ---------------- tf32 GEMM, cp.async double-buffered ----------------
// C[M,N] = op(A)[M,K] @ B[N,K]^T + bias ; A,B pre-rounded to tf32.
// Block 128x256, 8 warps (2x4), warp tile 64x64. BK=32.
#define GBM 128
#define GBN 256
#define BKP 36                       // padded row stride in u32 (144B, 16B-aligned)
#define A_BYTES (GBM * BKP * 4)      // 18432
#define B_BYTES (GBN * BKP * 4)      // 36864
#define STAGE_BYTES (A_BYTES + B_BYTES)  // 55296
#define GSMEM (2 * STAGE_BYTES)          // 110592

__device__ __forceinline__ void issue_tile(const float* __restrict__ A,
                                           const float* __restrict__ B,
                                           uint32_t sstage, int m0, int n0, int k0,
                                           int K, int N, int t)
{
    // A: 128 rows x 8 chunks of 16B
    #pragma unroll
    for (int i = 0; i < 4; i++) {
        int id = t + (i << 8);
        int row = id >> 3;
        int c4 = (id & 7) << 2;
        int rem = K - (k0 + c4);
        int bytes = rem >= 4 ? 16 : (rem > 0 ? rem * 4 : 0);
        const float* src = A + (size_t)(m0 + row) * K + (bytes ? (k0 + c4) : 0);
        cp16(sstage + row * 144 + (id & 7) * 16, src, bytes);
    }
    // B: 256 rows x 8 chunks of 16B
    #pragma unroll
    for (int i = 0; i < 8; i++) {
        int id = t + (i << 8);
        int row = id >> 3;
        int c4 = (id & 7) << 2;
        int rem = K - (k0 + c4);
        int bytes = rem >= 4 ? 16 : (rem > 0 ? rem * 4 : 0);
        if (n0 + row >= N) bytes = 0;
        const float* src = bytes ? (B + (size_t)(n0 + row) * K + k0 + c4) : B;
        cp16(sstage + A_BYTES + row * 144 + (id & 7) * 16, src, bytes);
    }
}

__global__ void __launch_bounds__(256, 1)
gemm_tf32(const float* __restrict__ A, const float* __restrict__ B,
          const float* __restrict__ bias, float* __restrict__ C,
          int M, int N, int K, int ldc, int relu_a)
{
    extern __shared__ __align__(16) char sm[];
    uint32_t sbase = smem_u32(sm);

    int t = threadIdx.x;
    int warp = t >> 5, lane = t & 31;
    int m0 = blockIdx.y * GBM;
    int n0 = blockIdx.x * GBN;
    int mbase = (warp & 1) * 64;
    int nbase = (warp >> 1) * 64;

    float acc[4][8][4];
    #pragma unroll
    for (int mi = 0; mi < 4; mi++)
        #pragma unroll
        for (int ni = 0; ni < 8; ni++)
            #pragma unroll
            for (int r = 0; r < 4; r++) acc[mi][ni][r] = 0.0f;

    int KT = (K + 31) >> 5;

    issue_tile(A, B, sbase, m0, n0, 0, K, N, t);
    cp_commit();

    for (int kt = 0; kt < KT; kt++) {
        int s = kt & 1;
        if (kt + 1 < KT) {
            issue_tile(A, B, sbase + (s ^ 1) * STAGE_BYTES, m0, n0, (kt + 1) << 5, K, N, t);
            cp_commit();
            cp_wait<1>();
        } else {
            cp_wait<0>();
        }
        __syncthreads();

        const uint32_t* As = (const uint32_t*)(sm + s * STAGE_BYTES);
        const uint32_t* Bs = (const uint32_t*)(sm + s * STAGE_BYTES + A_BYTES);

        #pragma unroll
        for (int kk = 0; kk < 4; kk++) {
            int col = kk * 8 + (lane & 3);
            uint32_t a[4][4];
            #pragma unroll
            for (int mi = 0; mi < 4; mi++) {
                int r = mbase + mi * 16 + (lane >> 2);
                a[mi][0] = As[r * BKP + col];
                a[mi][1] = As[(r + 8) * BKP + col];
                a[mi][2] = As[r * BKP + col + 4];
                a[mi][3] = As[(r + 8) * BKP + col + 4];
            }
            if (relu_a) {
                #pragma unroll
                for (int mi = 0; mi < 4; mi++)
                    #pragma unroll
                    for (int q = 0; q < 4; q++) {
                        float f = fmaxf(__uint_as_float(a[mi][q]), 0.0f);
                        a[mi][q] = __float_as_uint(f);
                    }
            }
            uint32_t b[8][2];
            #pragma unroll
            for (int ni = 0; ni < 8; ni++) {
                int nb = nbase + ni * 8 + (lane >> 2);
                b[ni][0] = Bs[nb * BKP + col];
                b[ni][1] = Bs[nb * BKP + col + 4];
            }
            #pragma unroll
            for (int mi = 0; mi < 4; mi++)
                #pragma unroll
                for (int ni = 0; ni < 8; ni++)
                    mma_tf32(acc[mi][ni], a[mi], b[ni][0], b[ni][1]);
        }
        __syncthreads();
    }

    // epilogue (writes tf32-rounded so downstream GEMMs can consume raw)
    #pragma unroll
    for (int mi = 0; mi < 4; mi++) {
        int r0 = m0 + mbase + mi * 16 + (lane >> 2);
        #pragma unroll
        for (int ni = 0; ni < 8; ni++) {
            int col = n0 + nbase + ni * 8 + (lane & 3) * 2;
            if (col < N) {
                float b0 = bias[col], b1 = bias[col + 1];
                C[(size_t)r0 * ldc + col]       = rnd_tf32(acc[mi][ni][0] + b0);
                C[(size_t)r0 * ldc + col + 1]   = rnd_tf32(acc[mi][ni][1] + b1);
                C[(size_t)(r0 + 8) * ldc + col]     = rnd_tf32(acc[mi][ni][2] + b0);
                C[(size_t)(r0 + 8) * ldc + col + 1] = rnd_tf32(acc[mi][ni][3] + b1);
            }
        }
    }
}

// ---------------- build kernel: gather + time encoding (tf32-rounded outputs) ----------------
__global__ void build_kernel(const int* __restrict__ nids,
                             const int* __restrict__ hist_nids,
                             const int* __restrict__ aids,
                             const int* __restrict__ eids,
                             const float* __restrict__ ts,
                             const int* __restrict__ dirs,
                             const float* __restrict__ node_emb,
                             const float* __restrict__ edge_emb,
                             const float* __restrict__ anony_emb,
                             const float* __restrict__ time_w,
                             const float* __restrict__ time_b,
                             float* __restrict__ out_pts)
{
    int row = blockIdx.x;
    int b = row / LH, l = row % LH;
    int hn  = hist_nids[row];
    int d   = dirs[row];
    int rn  = nids[b];
    int src = d ? rn : hn;
    int dst = d ? hn : rn;
    int aid = aids[row];
    int eid = eids[row];
    float tlast = ts[b*LH + (LH-1)];
    float dt = tlast - ts[row];
    bool last = (l == LH-1);
    float* Frow = g_F + (size_t)row * DD;

    for (int c = threadIdx.x; c < DD; c += blockDim.x) {
        float v;
        if      (c < 172) v = node_emb[(size_t)src*NF + c];
        else if (c < 344) v = node_emb[(size_t)dst*NF + (c-172)];
        else if (c < 516) v = anony_emb[(size_t)aid*NF + (c-344)];
        else if (c < 688) v = edge_emb[(size_t)eid*NF + (c-516)];
        else {
            int f = c - 688;
            v = cosf(dt * time_w[f] + time_b[f]);
        }
        v = rnd_tf32(v);
        if (last && c < LEF) {
            g_X[(size_t)b*DD + NF + c] = v;
            v = 0.0f;
        }
        Frow[c] = v;
    }
    if (last && threadIdx.x == 0) out_pts[b] = tlast;
}

// ---------------- attention + q-mean fused kernel -> ctx_mean[BS, D] ----------------
__global__ void __launch_bounds__(256)
attn_kernel(const int* __restrict__ hist_nids)
{
    __shared__ float Ks[LH * 432];
    __shared__ float sc[LH][LH];
    __shared__ float abar[LH];
    __shared__ int   msk[LH];

    int b = blockIdx.x;
    int t = threadIdx.x;
    int warp = t >> 5, lane = t & 31;
    const float* qkvb = g_QKV + (size_t)b * LH * QKVN;
    const float scale = 0.048224282f;   // 1/sqrt(430)

    if (t < LH) msk[t] = (hist_nids[b*LH + t] == 0 && t != LH-1) ? 1 : 0;

    for (int h = 0; h < 2; h++) {
        int off = h * DH;
        for (int i = t; i < LH*DH; i += 256) {
            int j = i / DH, dd = i % DH;
            Ks[j*432 + dd] = qkvb[(size_t)j*QKVN + DD + off + dd];
        }
        __syncthreads();

        for (int i = warp; i < LH; i += 8) {
            float accj[LH];
            #pragma unroll
            for (int j = 0; j < LH; j++) accj[j] = 0.f;
            const float* qrow = qkvb + (size_t)i*QKVN + off;
            for (int dd = lane; dd < DH; dd += 32) {
                float qv = qrow[dd];
                #pragma unroll
                for (int j = 0; j < LH; j++)
                    accj[j] += qv * Ks[j*432 + dd];
            }
            #pragma unroll
            for (int j = 0; j < LH; j++) {
                float s = accj[j];
                #pragma unroll
                for (int o = 16; o > 0; o >>= 1)
                    s += __shfl_xor_sync(0xffffffffu, s, o);
                if (lane == 0) sc[i][j] = s * scale;
            }
        }
        __syncthreads();

        if (warp == 0 && lane < LH) {
            int i = lane;
            float mx = -1e30f;
            #pragma unroll
            for (int j = 0; j < LH; j++)
                if (!msk[j]) mx = fmaxf(mx, sc[i][j]);
            float e[LH]; float s = 0.f;
            #pragma unroll
            for (int j = 0; j < LH; j++) {
                float ev = msk[j] ? 0.f : __expf(sc[i][j] - mx);
                e[j] = ev; s += ev;
            }
            float inv = 1.f / s;
            #pragma unroll
            for (int j = 0; j < LH; j++) sc[i][j] = e[j] * inv;
        }
        __syncthreads();

        if (warp == 0 && lane < LH) {
            int j = lane; float s = 0.f;
            #pragma unroll
            for (int i = 0; i < LH; i++) s += sc[i][j];
            abar[j] = s * (1.0f / LH);
        }
        __syncthreads();

        for (int dd = t; dd < DH; dd += 256) {
            float s = 0.f;
            #pragma unroll
            for (int j = 0; j < LH; j++)
                s += abar[j] * qkvb[(size_t)j*QKVN + 2*DD + off + dd];
            g_CTXM[(size_t)b*DD + off + dd] = rnd_tf32(s);
        }
        __syncthreads();
    }
}

// ---------------- copy h_prev_left into d_out ----------------
__global__ void copy_hl(float* __restrict__ out)
{
    int i = blockIdx.x * 256 + threadIdx.x;
    if (i < BS * NF) {
        int b = i / NF, c = i % NF;
        out[i] = g_X[(size_t)b*DD + c];
    }
}

// ---------------- launch ----------------
extern "C" void kernel_launch(void* const* d_in, const int* in_sizes, int n_in,
                              void* d_out, int out_size)
{
    const int*   nids       = (const int*)  d_in[0];
    const int*   hist_nids  = (const int*)  d_in[1];
    const int*   aids       = (const int*)  d_in[2];
    const int*   eids       = (const int*)  d_in[3];
    const float* hist_ts    = (const float*)d_in[4];
    const int*   dirs       = (const int*)  d_in[5];
    const float* node_emb   = (const float*)d_in[6];
    const float* edge_emb   = (const float*)d_in[7];
    const float* anony_emb  = (const float*)d_in[8];
    const float* time_w     = (const float*)d_in[9];
    const float* time_b     = (const float*)d_in[10];
    const float* in_proj_w  = (const float*)d_in[11];
    const float* in_proj_b  = (const float*)d_in[12];
    const float* out_proj_w = (const float*)d_in[13];
    const float* out_proj_b = (const float*)d_in[14];
    const float* outfn_w    = (const float*)d_in[15];
    const float* outfn_b    = (const float*)d_in[16];
    const float* fc1_w      = (const float*)d_in[17];
    const float* fc1_b      = (const float*)d_in[18];
    const float* fc2_w      = (const float*)d_in[19];
    const float* fc2_b      = (const float*)d_in[20];

    float* out = (float*)d_out;
    float* out_hr  = out + (size_t)BS * NF;
    float* out_pts = out + (size_t)2 * BS * NF;

    float* F    = nullptr; cudaGetSymbolAddress((void**)&F,    g_F);
    float* QKV  = nullptr; cudaGetSymbolAddress((void**)&QKV,  g_QKV);
    float* CTXM = nullptr; cudaGetSymbolAddress((void**)&CTXM, g_CTXM);
    float* OM   = nullptr; cudaGetSymbolAddress((void**)&OM,   g_OM);
    float* X    = nullptr; cudaGetSymbolAddress((void**)&X,    g_X);
    float* H1   = nullptr; cudaGetSymbolAddress((void**)&H1,   g_H1);
    float* WR   = nullptr; cudaGetSymbolAddress((void**)&WR,   g_WR);

    cudaFuncSetAttribute(gemm_tf32, cudaFuncAttributeMaxDynamicSharedMemorySize, GSMEM);

    // 0) pre-round all weights to tf32 (RNA) so GEMMs can stage raw via cp.async
    round_w<<<(QKVN*DD + 255)/256, 256>>>(in_proj_w,  WR + W_INPROJ,  QKVN*DD);
    round_w<<<(DD*DD   + 255)/256, 256>>>(out_proj_w, WR + W_OUTPROJ, DD*DD);
    round_w<<<(NF*DD   + 255)/256, 256>>>(outfn_w,    WR + W_OUTFN,   NF*DD);
    round_w<<<(NF*DD   + 255)/256, 256>>>(fc1_w,      WR + W_FC1,     NF*DD);
    round_w<<<(NF*NF   + 255)/256, 256>>>(fc2_w,      WR + W_FC2,     NF*NF);

    // 1) build features (tf32-rounded)
    build_kernel<<<NROWS, 256>>>(nids, hist_nids, aids, eids, hist_ts, dirs,
                                 node_emb, edge_emb, anony_emb, time_w, time_b,
                                 out_pts);

    // 2) qkv = F @ in_proj_w^T + b   [163840 x 2580]
    gemm_tf32<<<dim3((QKVN + GBN - 1)/GBN, NROWS/GBM), 256, GSMEM>>>(
        F, WR + W_INPROJ, in_proj_b, QKV, NROWS, QKVN, DD, QKVN, 0);

    // 3) attention (+ mean over queries)
    attn_kernel<<<BS, 256>>>(hist_nids);

    // 4) om = ctx_mean @ out_proj_w^T + b
    gemm_tf32<<<dim3((DD + GBN - 1)/GBN, BS/GBM), 256, GSMEM>>>(
        CTXM, WR + W_OUTPROJ, out_proj_b, OM, BS, DD, DD, DD, 0);

    // 5) h_prev_left = relu(om) @ outfn_w^T + b -> g_X cols [0,172)
    gemm_tf32<<<dim3((NF + GBN - 1)/GBN, BS/GBM), 256, GSMEM>>>(
        OM, WR + W_OUTFN, outfn_b, X, BS, NF, DD, DD, 1);

    // 6) copy h_prev_left to output
    copy_hl<<<(BS*NF + 255)/256, 256>>>(out);

    // 7) H1 = X @ fc1_w^T + b
    gemm_tf32<<<dim3((NF + GBN - 1)/GBN, BS/GBM), 256, GSMEM>>>(
        X, WR + W_FC1, fc1_b, H1, BS, NF, DD, NF, 0);

    // 8) h_prev_right = relu(H1) @ fc2_w^T + b
    gemm_tf32<<<dim3((NF + GBN - 1)/GBN, BS/GBM), 256, GSMEM>>>(
        H1, WR + W_FC2, fc2_b, out_hr, BS, NF, NF, NF, 1);
}

// round 4
// speedup vs baseline: 1.1824x; 1.0259x over previous
#include <cuda_runtime.h>
#include <cuda_bf16.h>
#include <cstdint>
#include <math.h>

// ---------------- problem constants ----------------
#define BS 8192
#define LH 20
#define NF 172
#define TF 172
#define DD 860            // D = NF*3 + NF + TF
#define DH 430            // D / H
#define NROWS (BS*LH)     // 163840
#define QKVN 2580         // 3*D
#define LEF 688           // D - TF

// weight scratch offsets (floats)
#define W_INPROJ 0
#define W_OUTPROJ (W_INPROJ + QKVN*DD)
#define W_OUTFN   (W_OUTPROJ + DD*DD)
#define W_FC1     (W_OUTFN + NF*DD)
#define W_FC2     (W_FC1 + NF*DD)
#define W_TOTAL   (W_FC2 + NF*NF)

// ---------------- scratch (__device__ globals) ----------------
__device__ float g_F[(size_t)NROWS * DD];
__device__ float g_QKV[(size_t)NROWS * QKVN];
__device__ float g_CTXM[(size_t)BS * DD];
__device__ float g_OM[(size_t)BS * DD];
__device__ float g_X[(size_t)BS * DD];
__device__ float g_H1[(size_t)BS * NF];
__device__ float g_WR[(size_t)W_TOTAL];

// ---------------- helpers ----------------
__device__ __forceinline__ uint32_t f2tf32(float x) {
    uint32_t u;
    asm("cvt.rna.tf32.f32 %0, %1;" : "=r"(u) : "f"(x));
    return u;
}
__device__ __forceinline__ float rnd_tf32(float x) {
    return __uint_as_float(f2tf32(x));
}
__device__ __forceinline__ uint32_t smem_u32(const void* p) {
    uint32_t a;
    asm("{ .reg .u64 t; cvta.to.shared.u64 t, %1; cvt.u32.u64 %0, t; }" : "=r"(a) : "l"(p));
    return a;
}
__device__ __forceinline__ void cp16(uint32_t dst, const void* src, int bytes) {
    asm volatile("cp.async.cg.shared.global [%0], [%1], 16, %2;"
                 :: "r"(dst), "l"(src), "r"(bytes));
}
__device__ __forceinline__ void cp_commit() {
    asm volatile("cp.async.commit_group;" ::: "memory");
}
template <int N>
__device__ __forceinline__ void cp_wait() {
    asm volatile("cp.async.wait_group %0;" :: "n"(N) : "memory");
}
__device__ __forceinline__ void mma_tf32(float* c, const uint32_t* a, uint32_t b0, uint32_t b1) {
    asm volatile(
        "mma.sync.aligned.m16n8k8.row.col.f32.tf32.tf32.f32 "
        "{%0,%1,%2,%3}, {%4,%5,%6,%7}, {%8,%9}, {%0,%1,%2,%3};\n"
        : "+f"(c[0]), "+f"(c[1]), "+f"(c[2]), "+f"(c[3])
        : "r"(a[0]), "r"(a[1]), "r"(a[2]), "r"(a[3]), "r"(b0), "r"(b1));
}

// ---------------- fused weight pre-round kernel ----------------
__global__ void round_all(const float* __restrict__ w_inproj,
                          const float* __restrict__ w_outproj,
                          const float* __restrict__ w_outfn,
                          const float* __restrict__ w_fc1,
                          const float* __restrict__ w_fc2)
{
    int i = blockIdx.x * 256 + threadIdx.x;
    if (i >= W_TOTAL) return;
    float v;
    if      (i < W_OUTPROJ) v = w_inproj[i - W_INPROJ];
    else if (i < W_OUTFN)   v = w_outproj[i - W_OUTPROJ];
    else if (i < W_FC1)     v = w_outfn[i - W_OUTFN];
    else if (i < W_FC2)     v = w_fc1[i - W_FC1];
    else                    v = w_fc2[i - W_FC2];
    g_WR[i] = rnd_tf32(v);
}

// ---------------- tf32 GEMM, 3-stage cp.async pipeline, 1 barrier/ktile ----------------
// C[M,N] = op(A)[M,K] @ B[N,K]^T + bias ; A,B pre-rounded to tf32.
// Block 128x256, 8 warps (2x4), warp tile 64x64. BK=32, 3 stages.
#define GBM 128
#define GBN 256
#define BKP 36                       // padded row stride in u32 (144B)
#define A_BYTES (GBM * BKP * 4)      // 18432
#define B_BYTES (GBN * BKP * 4)      // 36864
#define STAGE_BYTES (A_BYTES + B_BYTES)  // 55296
#define NSTAGE 3
#define GSMEM (NSTAGE * STAGE_BYTES)     // 165888

__device__ __forceinline__ void issue_tile(const float* __restrict__ A,
                                           const float* __restrict__ B,
                                           uint32_t sstage, int m0, int n0, int k0,
                                           int K, int N, int t)
{
    #pragma unroll
    for (int i = 0; i < 4; i++) {
        int id = t + (i << 8);
        int row = id >> 3;
        int c4 = (id & 7) << 2;
        int rem = K - (k0 + c4);
        int bytes = rem >= 4 ? 16 : (rem > 0 ? rem * 4 : 0);
        const float* src = A + (size_t)(m0 + row) * K + (bytes ? (k0 + c4) : 0);
        cp16(sstage + row * 144 + (id & 7) * 16, src, bytes);
    }
    #pragma unroll
    for (int i = 0; i < 8; i++) {
        int id = t + (i << 8);
        int row = id >> 3;
        int c4 = (id & 7) << 2;
        int rem = K - (k0 + c4);
        int bytes = rem >= 4 ? 16 : (rem > 0 ? rem * 4 : 0);
        if (n0 + row >= N) bytes = 0;
        const float* src = bytes ? (B + (size_t)(n0 + row) * K + k0 + c4) : B;
        cp16(sstage + A_BYTES + row * 144 + (id & 7) * 16, src, bytes);
    }
}

__global__ void __launch_bounds__(256, 1)
gemm_tf32(const float* __restrict__ A, const float* __restrict__ B,
          const float* __restrict__ bias, float* __restrict__ C,
          int M, int N, int K, int ldc, int relu_a, float* __restrict__ aux)
{
    extern __shared__ __align__(16) char sm[];
    uint32_t sbase = smem_u32(sm);

    int t = threadIdx.x;
    int warp = t >> 5, lane = t & 31;
    int m0 = blockIdx.y * GBM;
    int n0 = blockIdx.x * GBN;
    int mbase = (warp & 1) * 64;
    int nbase = (warp >> 1) * 64;

    float acc[4][8][4];
    #pragma unroll
    for (int mi = 0; mi < 4; mi++)
        #pragma unroll
        for (int ni = 0; ni < 8; ni++)
            #pragma unroll
            for (int r = 0; r < 4; r++) acc[mi][ni][r] = 0.0f;

    int KT = (K + 31) >> 5;

    // prologue: prefetch tiles 0 and 1
    issue_tile(A, B, sbase, m0, n0, 0, K, N, t);
    cp_commit();
    if (KT > 1)
        issue_tile(A, B, sbase + STAGE_BYTES, m0, n0, 32, K, N, t);
    cp_commit();

    int scur = 0, snxt = 2;
    for (int kt = 0; kt < KT; kt++) {
        cp_wait<1>();
        __syncthreads();     // stage scur ready; all warps done with stage snxt's old data

        if (kt + 2 < KT)
            issue_tile(A, B, sbase + snxt * STAGE_BYTES, m0, n0, (kt + 2) << 5, K, N, t);
        cp_commit();

        const uint32_t* As = (const uint32_t*)(sm + scur * STAGE_BYTES);
        const uint32_t* Bs = (const uint32_t*)(sm + scur * STAGE_BYTES + A_BYTES);

        #pragma unroll
        for (int kk = 0; kk < 4; kk++) {
            int col = kk * 8 + (lane & 3);
            uint32_t a[4][4];
            #pragma unroll
            for (int mi = 0; mi < 4; mi++) {
                int r = mbase + mi * 16 + (lane >> 2);
                a[mi][0] = As[r * BKP + col];
                a[mi][1] = As[(r + 8) * BKP + col];
                a[mi][2] = As[r * BKP + col + 4];
                a[mi][3] = As[(r + 8) * BKP + col + 4];
            }
            if (relu_a) {
                #pragma unroll
                for (int mi = 0; mi < 4; mi++)
                    #pragma unroll
                    for (int q = 0; q < 4; q++) {
                        float f = fmaxf(__uint_as_float(a[mi][q]), 0.0f);
                        a[mi][q] = __float_as_uint(f);
                    }
            }
            uint32_t b[8][2];
            #pragma unroll
            for (int ni = 0; ni < 8; ni++) {
                int nb = nbase + ni * 8 + (lane >> 2);
                b[ni][0] = Bs[nb * BKP + col];
                b[ni][1] = Bs[nb * BKP + col + 4];
            }
            #pragma unroll
            for (int mi = 0; mi < 4; mi++)
                #pragma unroll
                for (int ni = 0; ni < 8; ni++)
                    mma_tf32(acc[mi][ni], a[mi], b[ni][0], b[ni][1]);
        }

        scur = (scur == NSTAGE - 1) ? 0 : scur + 1;
        snxt = (snxt == NSTAGE - 1) ? 0 : snxt + 1;
    }

    // epilogue (tf32-rounded so downstream GEMMs consume raw)
    #pragma unroll
    for (int mi = 0; mi < 4; mi++) {
        int r0 = m0 + mbase + mi * 16 + (lane >> 2);
        #pragma unroll
        for (int ni = 0; ni < 8; ni++) {
            int col = n0 + nbase + ni * 8 + (lane & 3) * 2;
            if (col < N) {
                float b0 = bias[col], b1 = bias[col + 1];
                float v00 = rnd_tf32(acc[mi][ni][0] + b0);
                float v01 = rnd_tf32(acc[mi][ni][1] + b1);
                float v10 = rnd_tf32(acc[mi][ni][2] + b0);
                float v11 = rnd_tf32(acc[mi][ni][3] + b1);
                C[(size_t)r0 * ldc + col]           = v00;
                C[(size_t)r0 * ldc + col + 1]       = v01;
                C[(size_t)(r0 + 8) * ldc + col]     = v10;
                C[(size_t)(r0 + 8) * ldc + col + 1] = v11;
                if (aux) {
                    aux[(size_t)r0 * N + col]           = v00;
                    aux[(size_t)r0 * N + col + 1]       = v01;
                    aux[(size_t)(r0 + 8) * N + col]     = v10;
                    aux[(size_t)(r0 + 8) * N + col + 1] = v11;
                }
            }
        }
    }
}

// ---------------- build kernel: gather + time encoding (tf32-rounded outputs) ----------------
__global__ void build_kernel(const int* __restrict__ nids,
                             const int* __restrict__ hist_nids,
                             const int* __restrict__ aids,
                             const int* __restrict__ eids,
                             const float* __restrict__ ts,
                             const int* __restrict__ dirs,
                             const float* __restrict__ node_emb,
                             const float* __restrict__ edge_emb,
                             const float* __restrict__ anony_emb,
                             const float* __restrict__ time_w,
                             const float* __restrict__ time_b,
                             float* __restrict__ out_pts)
{
    int row = blockIdx.x;
    int b = row / LH, l = row % LH;
    int hn  = hist_nids[row];
    int d   = dirs[row];
    int rn  = nids[b];
    int src = d ? rn : hn;
    int dst = d ? hn : rn;
    int aid = aids[row];
    int eid = eids[row];
    float tlast = ts[b*LH + (LH-1)];
    float dt = tlast - ts[row];
    bool last = (l == LH-1);
    float* Frow = g_F + (size_t)row * DD;

    for (int c = threadIdx.x; c < DD; c += blockDim.x) {
        float v;
        if      (c < 172) v = node_emb[(size_t)src*NF + c];
        else if (c < 344) v = node_emb[(size_t)dst*NF + (c-172)];
        else if (c < 516) v = anony_emb[(size_t)aid*NF + (c-344)];
        else if (c < 688) v = edge_emb[(size_t)eid*NF + (c-516)];
        else {
            int f = c - 688;
            v = cosf(dt * time_w[f] + time_b[f]);
        }
        v = rnd_tf32(v);
        if (last && c < LEF) {
            g_X[(size_t)b*DD + NF + c] = v;
            v = 0.0f;
        }
        Frow[c] = v;
    }
    if (last && threadIdx.x == 0) out_pts[b] = tlast;
}

// ---------------- attention + q-mean fused kernel -> ctx_mean[BS, D] ----------------
__global__ void __launch_bounds__(256)
attn_kernel(const int* __restrict__ hist_nids)
{
    __shared__ float Ks[LH * 432];
    __shared__ float sc[LH][LH];
    __shared__ float abar[LH];
    __shared__ int   msk[LH];

    int b = blockIdx.x;
    int t = threadIdx.x;
    int warp = t >> 5, lane = t & 31;
    const float* qkvb = g_QKV + (size_t)b * LH * QKVN;
    const float scale = 0.048224282f;   // 1/sqrt(430)

    if (t < LH) msk[t] = (hist_nids[b*LH + t] == 0 && t != LH-1) ? 1 : 0;

    for (int h = 0; h < 2; h++) {
        int off = h * DH;
        for (int i = t; i < LH*DH; i += 256) {
            int j = i / DH, dd = i % DH;
            Ks[j*432 + dd] = qkvb[(size_t)j*QKVN + DD + off + dd];
        }
        __syncthreads();

        for (int i = warp; i < LH; i += 8) {
            float accj[LH];
            #pragma unroll
            for (int j = 0; j < LH; j++) accj[j] = 0.f;
            const float* qrow = qkvb + (size_t)i*QKVN + off;
            for (int dd = lane; dd < DH; dd += 32) {
                float qv = qrow[dd];
                #pragma unroll
                for (int j = 0; j < LH; j++)
                    accj[j] += qv * Ks[j*432 + dd];
            }
            #pragma unroll
            for (int j = 0; j < LH; j++) {
                float s = accj[j];
                #pragma unroll
                for (int o = 16; o > 0; o >>= 1)
                    s += __shfl_xor_sync(0xffffffffu, s, o);
                if (lane == 0) sc[i][j] = s * scale;
            }
        }
        __syncthreads();

        if (warp == 0 && lane < LH) {
            int i = lane;
            float mx = -1e30f;
            #pragma unroll
            for (int j = 0; j < LH; j++)
                if (!msk[j]) mx = fmaxf(mx, sc[i][j]);
            float e[LH]; float s = 0.f;
            #pragma unroll
            for (int j = 0; j < LH; j++) {
                float ev = msk[j] ? 0.f : __expf(sc[i][j] - mx);
                e[j] = ev; s += ev;
            }
            float inv = 1.f / s;
            #pragma unroll
            for (int j = 0; j < LH; j++) sc[i][j] = e[j] * inv;
        }
        __syncthreads();

        if (warp == 0 && lane < LH) {
            int j = lane; float s = 0.f;
            #pragma unroll
            for (int i = 0; i < LH; i++) s += sc[i][j];
            abar[j] = s * (1.0f / LH);
        }
        __syncthreads();

        for (int dd = t; dd < DH; dd += 256) {
            float s = 0.f;
            #pragma unroll
            for (int j = 0; j < LH; j++)
                s += abar[j] * qkvb[(size_t)j*QKVN + 2*DD + off + dd];
            g_CTXM[(size_t)b*DD + off + dd] = rnd_tf32(s);
        }
        __syncthreads();
    }
}

// ---------------- launch ----------------
extern "C" void kernel_launch(void* const* d_in, const int* in_sizes, int n_in,
                              void* d_out, int out_size)
{
    const int*   nids       = (const int*)  d_in[0];
    const int*   hist_nids  = (const int*)  d_in[1];
    const int*   aids       = (const int*)  d_in[2];
    const int*   eids       = (const int*)  d_in[3];
    const float* hist_ts    = (const float*)d_in[4];
    const int*   dirs       = (const int*)  d_in[5];
    const float* node_emb   = (const float*)d_in[6];
    const float* edge_emb   = (const float*)d_in[7];
    const float* anony_emb  = (const float*)d_in[8];
    const float* time_w     = (const float*)d_in[9];
    const float* time_b     = (const float*)d_in[10];
    const float* in_proj_w  = (const float*)d_in[11];
    const float* in_proj_b  = (const float*)d_in[12];
    const float* out_proj_w = (const float*)d_in[13];
    const float* out_proj_b = (const float*)d_in[14];
    const float* outfn_w    = (const float*)d_in[15];
    const float* outfn_b    = (const float*)d_in[16];
    const float* fc1_w      = (const float*)d_in[17];
    const float* fc1_b      = (const float*)d_in[18];
    const float* fc2_w      = (const float*)d_in[19];
    const float* fc2_b      = (const float*)d_in[20];

    float* out = (float*)d_out;
    float* out_hr  = out + (size_t)BS * NF;
    float* out_pts = out + (size_t)2 * BS * NF;

    float* F    = nullptr; cudaGetSymbolAddress((void**)&F,    g_F);
    float* QKV  = nullptr; cudaGetSymbolAddress((void**)&QKV,  g_QKV);
    float* CTXM = nullptr; cudaGetSymbolAddress((void**)&CTXM, g_CTXM);
    float* OM   = nullptr; cudaGetSymbolAddress((void**)&OM,   g_OM);
    float* X    = nullptr; cudaGetSymbolAddress((void**)&X,    g_X);
    float* H1   = nullptr; cudaGetSymbolAddress((void**)&H1,   g_H1);
    float* WR   = nullptr; cudaGetSymbolAddress((void**)&WR,   g_WR);

    cudaFuncSetAttribute(gemm_tf32, cudaFuncAttributeMaxDynamicSharedMemorySize, GSMEM);

    // 0) pre-round all weights to tf32 (single launch)
    round_all<<<(W_TOTAL + 255)/256, 256>>>(in_proj_w, out_proj_w, outfn_w, fc1_w, fc2_w);

    // 1) build features (tf32-rounded)
    build_kernel<<<NROWS, 256>>>(nids, hist_nids, aids, eids, hist_ts, dirs,
                                 node_emb, edge_emb, anony_emb, time_w, time_b,
                                 out_pts);

    // 2) qkv = F @ in_proj_w^T + b   [163840 x 2580]
    gemm_tf32<<<dim3((QKVN + GBN - 1)/GBN, NROWS/GBM), 256, GSMEM>>>(
        F, WR + W_INPROJ, in_proj_b, QKV, NROWS, QKVN, DD, QKVN, 0, nullptr);

    // 3) attention (+ mean over queries)
    attn_kernel<<<BS, 256>>>(hist_nids);

    // 4) om = ctx_mean @ out_proj_w^T + b
    gemm_tf32<<<dim3((DD + GBN - 1)/GBN, BS/GBM), 256, GSMEM>>>(
        CTXM, WR + W_OUTPROJ, out_proj_b, OM, BS, DD, DD, DD, 0, nullptr);

    // 5) h_prev_left = relu(om) @ outfn_w^T + b -> g_X cols [0,172) AND d_out
    gemm_tf32<<<dim3((NF + GBN - 1)/GBN, BS/GBM), 256, GSMEM>>>(
        OM, WR + W_OUTFN, outfn_b, X, BS, NF, DD, DD, 1, out);

    // 6) H1 = X @ fc1_w^T + b
    gemm_tf32<<<dim3((NF + GBN - 1)/GBN, BS/GBM), 256, GSMEM>>>(
        X, WR + W_FC1, fc1_b, H1, BS, NF, DD, NF, 0, nullptr);

    // 7) h_prev_right = relu(H1) @ fc2_w^T + b
    gemm_tf32<<<dim3((NF + GBN - 1)/GBN, BS/GBM), 256, GSMEM>>>(
        H1, WR + W_FC2, fc2_b, out_hr, BS, NF, NF, NF, 1, nullptr);
}